// round 4
// baseline (speedup 1.0000x reference)
#include <cuda_runtime.h>
#include <math.h>
#include <stdint.h>

#define NTOK 8192
#define DDIM 1024
#define APW  249            // band: |i-j| <= 249
#define BANDW 512           // raw logits band stride
#define SBW  768            // split-att band stride (with zero margins)
#define SBOFF 128           // left margin of split-att rows

// ---------------- scratch (static device arrays; zero-initialized) ----------------
__device__ float g_xh [(size_t)NTOK * DDIM];
__device__ float g_xl [(size_t)NTOK * DDIM];
__device__ float g_Wqh[DDIM * DDIM];
__device__ float g_Wql[DDIM * DDIM];
__device__ float g_Wkh[DDIM * DDIM];
__device__ float g_Wkl[DDIM * DDIM];
__device__ float g_Wvr[DDIM * DDIM];
__device__ float g_Wor[DDIM * DDIM];
__device__ float g_Q  [(size_t)NTOK * DDIM];   // tf32-rounded
__device__ float g_K  [(size_t)NTOK * DDIM];   // tf32-rounded
__device__ float g_V  [(size_t)NTOK * DDIM];   // tf32-rounded
__device__ float g_S  [(size_t)NTOK * BANDW];  // raw logits band
__device__ float g_Sh [(size_t)NTOK * SBW];    // att hi (margins stay zero)
__device__ float g_Sl [(size_t)NTOK * SBW];    // att lo
__device__ float g_y0h[(size_t)NTOK * DDIM];
__device__ float g_y0l[(size_t)NTOK * DDIM];

// ---------------- helpers ----------------
__device__ __forceinline__ uint32_t f2tf32(float f) {
    uint32_t u;
    asm("cvt.rna.tf32.f32 %0, %1;" : "=r"(u) : "f"(f));
    return u;
}
__device__ __forceinline__ float tf32f(float f) { return __uint_as_float(f2tf32(f)); }

__device__ __forceinline__ void mma_tf32(float c[4], const uint32_t a[4], const uint32_t b[2]) {
    asm volatile(
        "mma.sync.aligned.m16n8k8.row.col.f32.tf32.tf32.f32 "
        "{%0,%1,%2,%3}, {%4,%5,%6,%7}, {%8,%9}, {%0,%1,%2,%3};"
        : "+f"(c[0]), "+f"(c[1]), "+f"(c[2]), "+f"(c[3])
        : "r"(a[0]), "r"(a[1]), "r"(a[2]), "r"(a[3]), "r"(b[0]), "r"(b[1]));
}

__device__ __forceinline__ uint32_t s2u(const void* p) {
    return (uint32_t)__cvta_generic_to_shared(p);
}
__device__ __forceinline__ void cpa16(uint32_t dst, const float* src) {
    asm volatile("cp.async.cg.shared.global [%0], [%1], 16;" :: "r"(dst), "l"(src));
}
__device__ __forceinline__ void cpa16p(uint32_t dst, const float* src, bool ok) {
    int sz = ok ? 16 : 0;
    asm volatile("cp.async.cg.shared.global [%0], [%1], 16, %2;" :: "r"(dst), "l"(src), "r"(sz));
}
#define CPA_COMMIT() asm volatile("cp.async.commit_group;")
#define CPA_WAIT1()  asm volatile("cp.async.wait_group 1;")

// ---------------- prep: split / round ----------------
__global__ void split_k(const float* __restrict__ src, float* __restrict__ hi,
                        float* __restrict__ lo, int n) {
    int i = blockIdx.x * blockDim.x + threadIdx.x;
    if (i < n) {
        float v = src[i];
        float h = tf32f(v);
        hi[i] = h;
        lo[i] = tf32f(v - h);
    }
}
__global__ void round_k(const float* __restrict__ src, float* __restrict__ dst, int n) {
    int i = blockIdx.x * blockDim.x + threadIdx.x;
    if (i < n) dst[i] = tf32f(src[i]);
}

// =====================================================================
// Pipelined tf32 GEMM engine: C = alpha * (Ah+Al) @ (Bh+Bl)^T
// terms: hh (+ lh if AL) (+ hl if BL).  128x128x16 tiles, 2-stage cp.async.
// OUT: 0 = plain fp32, 1 = tf32-rounded, 2 = split (C=hi, C2=lo)
// =====================================================================
#define EST 20
#define ETS (128 * EST)

template<int AL, int BL, int OUT>
__global__ __launch_bounds__(256) void gemm_pipe(
    const float* __restrict__ Ah, const float* __restrict__ Al,
    const float* __restrict__ Bh, const float* __restrict__ Bl,
    float* __restrict__ C, float* __restrict__ C2,
    int M, int N, int K, float alpha)
{
    extern __shared__ float sm[];
    float* sAh = sm;
    float* sAl = sAh + 2 * ETS;
    float* sBh = sAl + (AL ? 2 * ETS : 0);
    float* sBl = sBh + 2 * ETS;

    const int t = threadIdx.x;
    const int warp = t >> 5, lane = t & 31;
    const int g = lane >> 2, tig = lane & 3;
    const int wm = warp >> 2, wn = warp & 3;

    const int rowA0 = blockIdx.y * 128;
    const int rowB0 = blockIdx.x * 128;

    const int lr = t >> 1;
    const int lc = (t & 1) * 8;

    const float* gAh = Ah + (size_t)(rowA0 + lr) * K + lc;
    const float* gAl = AL ? (Al + (size_t)(rowA0 + lr) * K + lc) : Ah;
    const float* gBh = Bh + (size_t)(rowB0 + lr) * K + lc;
    const float* gBl = BL ? (Bl + (size_t)(rowB0 + lr) * K + lc) : Bh;

    const int sOff = lr * EST + lc;
    const uint32_t dAh = s2u(sAh + sOff);
    const uint32_t dAl = s2u(sAl + sOff);
    const uint32_t dBh = s2u(sBh + sOff);
    const uint32_t dBl = s2u(sBl + sOff);

    float acc[4][4][4] = {};

    auto issue = [&](int kt, int s) {
        const int k0 = kt * 16;
        const uint32_t so = (uint32_t)(s * ETS * 4);
        cpa16(dAh + so, gAh + k0);      cpa16(dAh + so + 16, gAh + k0 + 4);
        if (AL) { cpa16(dAl + so, gAl + k0); cpa16(dAl + so + 16, gAl + k0 + 4); }
        cpa16(dBh + so, gBh + k0);      cpa16(dBh + so + 16, gBh + k0 + 4);
        if (BL) { cpa16(dBl + so, gBl + k0); cpa16(dBl + so + 16, gBl + k0 + 4); }
    };

    const int KT = K / 16;
    issue(0, 0);
    CPA_COMMIT();

    for (int kt = 0; kt < KT; kt++) {
        const int s = kt & 1;
        if (kt + 1 < KT) issue(kt + 1, s ^ 1);
        CPA_COMMIT();
        CPA_WAIT1();
        __syncthreads();

        const float* pA  = sAh + s * ETS;
        const float* pAl = sAl + s * ETS;
        const float* pB  = sBh + s * ETS;
        const float* pBl = sBl + s * ETS;

        #pragma unroll
        for (int k8 = 0; k8 < 2; k8++) {
            const int kk = k8 * 8 + tig;
            uint32_t ah[4][4], al[4][4], bh[4][2], bl[4][2];
            #pragma unroll
            for (int fm = 0; fm < 4; fm++) {
                const int m = wm * 64 + fm * 16 + g;
                ah[fm][0] = __float_as_uint(pA[m * EST + kk]);
                ah[fm][1] = __float_as_uint(pA[(m + 8) * EST + kk]);
                ah[fm][2] = __float_as_uint(pA[m * EST + kk + 4]);
                ah[fm][3] = __float_as_uint(pA[(m + 8) * EST + kk + 4]);
                if (AL) {
                    al[fm][0] = __float_as_uint(pAl[m * EST + kk]);
                    al[fm][1] = __float_as_uint(pAl[(m + 8) * EST + kk]);
                    al[fm][2] = __float_as_uint(pAl[m * EST + kk + 4]);
                    al[fm][3] = __float_as_uint(pAl[(m + 8) * EST + kk + 4]);
                }
            }
            #pragma unroll
            for (int fn = 0; fn < 4; fn++) {
                const int n = wn * 32 + fn * 8 + g;
                bh[fn][0] = __float_as_uint(pB[n * EST + kk]);
                bh[fn][1] = __float_as_uint(pB[n * EST + kk + 4]);
                if (BL) {
                    bl[fn][0] = __float_as_uint(pBl[n * EST + kk]);
                    bl[fn][1] = __float_as_uint(pBl[n * EST + kk + 4]);
                }
            }
            #pragma unroll
            for (int fm = 0; fm < 4; fm++)
                #pragma unroll
                for (int fn = 0; fn < 4; fn++) {
                    mma_tf32(acc[fm][fn], ah[fm], bh[fn]);
                    if (AL) mma_tf32(acc[fm][fn], al[fm], bh[fn]);
                    if (BL) mma_tf32(acc[fm][fn], ah[fm], bl[fn]);
                }
        }
        __syncthreads();
    }

    #pragma unroll
    for (int fm = 0; fm < 4; fm++) {
        const int m0 = rowA0 + wm * 64 + fm * 16 + g;
        #pragma unroll
        for (int fn = 0; fn < 4; fn++) {
            const int n0 = rowB0 + wn * 32 + fn * 8 + 2 * tig;
            #pragma unroll
            for (int half = 0; half < 2; half++) {
                const size_t base = (size_t)(m0 + half * 8) * N + n0;
                #pragma unroll
                for (int c = 0; c < 2; c++) {
                    float v = alpha * acc[fm][fn][half * 2 + c];
                    if (OUT == 0) C[base + c] = v;
                    else if (OUT == 1) C[base + c] = tf32f(v);
                    else {
                        float h = tf32f(v);
                        C[base + c]  = h;
                        C2[base + c] = tf32f(v - h);
                    }
                }
            }
        }
    }
}

// =====================================================================
// Banded logits via tf32 mma: g_S[i][j-i+249] = Q[i,:].K[j,:]
// 128x128 tiles, j0 = i0-249+128*bx (bx 0..4), predicated K rows.
// =====================================================================
__global__ __launch_bounds__(256) void qk_mma()
{
    __shared__ float sQ[2 * ETS];
    __shared__ float sK[2 * ETS];

    const int t = threadIdx.x;
    const int warp = t >> 5, lane = t & 31;
    const int g = lane >> 2, tig = lane & 3;
    const int wm = warp >> 2, wn = warp & 3;

    const int i0 = blockIdx.y * 128;
    const int j0 = i0 - APW + (int)blockIdx.x * 128;

    const int lr = t >> 1;
    const int lc = (t & 1) * 8;
    const int jr = j0 + lr;
    const bool jok = ((unsigned)jr < (unsigned)NTOK);
    const int jrc = jok ? jr : 0;

    const float* gQ = g_Q + (size_t)(i0 + lr) * DDIM + lc;
    const float* gK = g_K + (size_t)jrc * DDIM + lc;

    const int sOff = lr * EST + lc;
    const uint32_t dQ = s2u(sQ + sOff);
    const uint32_t dK = s2u(sK + sOff);

    float acc[4][4][4] = {};

    auto issue = [&](int kt, int s) {
        const int k0 = kt * 16;
        const uint32_t so = (uint32_t)(s * ETS * 4);
        cpa16 (dQ + so, gQ + k0);           cpa16 (dQ + so + 16, gQ + k0 + 4);
        cpa16p(dK + so, gK + k0, jok);      cpa16p(dK + so + 16, gK + k0 + 4, jok);
    };

    issue(0, 0);
    CPA_COMMIT();

    for (int kt = 0; kt < DDIM / 16; kt++) {
        const int s = kt & 1;
        if (kt + 1 < DDIM / 16) issue(kt + 1, s ^ 1);
        CPA_COMMIT();
        CPA_WAIT1();
        __syncthreads();

        const float* pQ = sQ + s * ETS;
        const float* pK = sK + s * ETS;

        #pragma unroll
        for (int k8 = 0; k8 < 2; k8++) {
            const int kk = k8 * 8 + tig;
            uint32_t a[4][4], b[4][2];
            #pragma unroll
            for (int fm = 0; fm < 4; fm++) {
                const int m = wm * 64 + fm * 16 + g;
                a[fm][0] = __float_as_uint(pQ[m * EST + kk]);
                a[fm][1] = __float_as_uint(pQ[(m + 8) * EST + kk]);
                a[fm][2] = __float_as_uint(pQ[m * EST + kk + 4]);
                a[fm][3] = __float_as_uint(pQ[(m + 8) * EST + kk + 4]);
            }
            #pragma unroll
            for (int fn = 0; fn < 4; fn++) {
                const int n = wn * 32 + fn * 8 + g;
                b[fn][0] = __float_as_uint(pK[n * EST + kk]);
                b[fn][1] = __float_as_uint(pK[n * EST + kk + 4]);
            }
            #pragma unroll
            for (int fm = 0; fm < 4; fm++)
                #pragma unroll
                for (int fn = 0; fn < 4; fn++)
                    mma_tf32(acc[fm][fn], a[fm], b[fn]);
        }
        __syncthreads();
    }

    // band-masked store
    #pragma unroll
    for (int fm = 0; fm < 4; fm++) {
        #pragma unroll
        for (int half = 0; half < 2; half++) {
            const int i = i0 + wm * 64 + fm * 16 + g + half * 8;
            #pragma unroll
            for (int fn = 0; fn < 4; fn++) {
                const int jb = j0 + wn * 32 + fn * 8 + 2 * tig;
                #pragma unroll
                for (int c = 0; c < 2; c++) {
                    const int j = jb + c;
                    const int tt = j - i + APW;
                    if ((unsigned)j < (unsigned)NTOK && (unsigned)tt <= (unsigned)(2 * APW))
                        g_S[(size_t)i * BANDW + tt] = acc[fm][fn][half * 2 + c];
                }
            }
        }
    }
}

// =====================================================================
// Per-row band softmax -> d_att (fp32) + split att (g_Sh/g_Sl, stride 768)
// =====================================================================
__global__ __launch_bounds__(256) void softmax_band_kernel(float* __restrict__ d_att,
                                                           int write_att)
{
    const int i = blockIdx.x;
    const int t = threadIdx.x;
    const int t_lo = (i < APW) ? (APW - i) : 0;
    const int jmax = (i + APW < NTOK - 1) ? (i + APW) : (NTOK - 1);
    const int t_hi = jmax - i + APW;

    const float* row = g_S + (size_t)i * BANDW;
    const int t0 = t, t1 = t + 256;
    float v0 = (t0 >= t_lo && t0 <= t_hi) ? row[t0] : -INFINITY;
    float v1 = (t1 >= t_lo && t1 <= t_hi) ? row[t1] : -INFINITY;

    __shared__ float shm[8];
    __shared__ float shs[8];
    const int lane = t & 31, warp = t >> 5;

    float m = fmaxf(v0, v1);
    #pragma unroll
    for (int o = 16; o > 0; o >>= 1) m = fmaxf(m, __shfl_xor_sync(0xffffffffu, m, o));
    if (lane == 0) shm[warp] = m;
    __syncthreads();
    if (warp == 0) {
        float mm = (lane < 8) ? shm[lane] : -INFINITY;
        #pragma unroll
        for (int o = 4; o > 0; o >>= 1) mm = fmaxf(mm, __shfl_xor_sync(0xffffffffu, mm, o));
        if (lane == 0) shm[0] = mm;
    }
    __syncthreads();
    const float M = shm[0];

    const float e0 = expf(v0 - M);
    const float e1 = expf(v1 - M);
    float s = e0 + e1;
    #pragma unroll
    for (int o = 16; o > 0; o >>= 1) s += __shfl_xor_sync(0xffffffffu, s, o);
    if (lane == 0) shs[warp] = s;
    __syncthreads();
    if (warp == 0) {
        float ss = (lane < 8) ? shs[lane] : 0.f;
        #pragma unroll
        for (int o = 4; o > 0; o >>= 1) ss += __shfl_xor_sync(0xffffffffu, ss, o);
        if (lane == 0) shs[0] = ss;
    }
    __syncthreads();
    const float inv = 1.0f / shs[0];

    float* rowh = g_Sh + (size_t)i * SBW + SBOFF;
    float* rowl = g_Sl + (size_t)i * SBW + SBOFF;

    if (t0 >= t_lo && t0 <= t_hi) {
        const float w = e0 * inv;
        const float h = tf32f(w);
        rowh[t0] = h;
        rowl[t0] = tf32f(w - h);
        if (write_att) d_att[(size_t)i * NTOK + (i - APW + t0)] = w;
    }
    if (t1 >= t_lo && t1 <= t_hi) {
        const float w = e1 * inv;
        const float h = tf32f(w);
        rowh[t1] = h;
        rowl[t1] = tf32f(w - h);
        if (write_att) d_att[(size_t)i * NTOK + (i - APW + t1)] = w;
    }
}

// =====================================================================
// y0[j,d] = sum_i att[i,j]*V[i,d], 2-term (att split), tf32 mma.
// 128(j) x 128(d) tiles, i chunked by 16 over [j0-256, j0+384).
// Output split into g_y0h/g_y0l.
// =====================================================================
#define AST 132
#define ATS (16 * AST)

__global__ __launch_bounds__(256) void attv_mma()
{
    extern __shared__ float sm[];
    float* sAh = sm;                 // [2][ATS]
    float* sAl = sAh + 2 * ATS;
    float* sV  = sAl + 2 * ATS;      // [2][ATS]

    const int t = threadIdx.x;
    const int warp = t >> 5, lane = t & 31;
    const int g = lane >> 2, tig = lane & 3;
    const int wm = warp >> 2, wn = warp & 3;

    const int j0 = blockIdx.y * 128;
    const int d0 = blockIdx.x * 128;
    const int iStart = j0 - 256;

    const int ar = t >> 4;           // 0..15
    const int ac = (t & 15) * 8;     // 0..120
    const uint32_t dV = s2u(sV + ar * AST + ac);

    float acc[4][4][4] = {};
    float rah[8], ral[8];

    auto ldA = [&](int kt) {
        const int i = iStart + kt * 16 + ar;
        const bool ok = ((unsigned)i < (unsigned)NTOK);
        const int ic = ok ? i : 0;
        const float* ph = g_Sh + (size_t)ic * SBW + (j0 - ic + APW + SBOFF) + ac;
        const float* pl = g_Sl + (size_t)ic * SBW + (j0 - ic + APW + SBOFF) + ac;
        #pragma unroll
        for (int u = 0; u < 8; u++) {
            rah[u] = ok ? ph[u] : 0.f;
            ral[u] = ok ? pl[u] : 0.f;
        }
    };
    auto issueV = [&](int kt, int s) {
        const int i = iStart + kt * 16 + ar;
        const bool ok = ((unsigned)i < (unsigned)NTOK);
        const int ic = ok ? i : 0;
        const float* pv = g_V + (size_t)ic * DDIM + d0 + ac;
        const uint32_t so = (uint32_t)(s * ATS * 4);
        cpa16p(dV + so, pv, ok);
        cpa16p(dV + so + 16, pv + 4, ok);
    };

    issueV(0, 0);
    CPA_COMMIT();
    ldA(0);

    const int KT = 40;   // 640 i values
    for (int kt = 0; kt < KT; kt++) {
        const int s = kt & 1;
        __syncthreads();          // stage s fully consumed by compute(kt-2)
        float* wAh = sAh + s * ATS + ar * AST + ac;
        float* wAl = sAl + s * ATS + ar * AST + ac;
        #pragma unroll
        for (int u = 0; u < 8; u++) { wAh[u] = rah[u]; wAl[u] = ral[u]; }
        if (kt + 1 < KT) issueV(kt + 1, s ^ 1);
        CPA_COMMIT();
        if (kt + 1 < KT) ldA(kt + 1);
        CPA_WAIT1();
        __syncthreads();

        const float* pAh = sAh + s * ATS;
        const float* pAl = sAl + s * ATS;
        const float* pV  = sV  + s * ATS;

        #pragma unroll
        for (int k8 = 0; k8 < 2; k8++) {
            const int kk = k8 * 8 + tig;
            uint32_t ah[4][4], al[4][4], bv[4][2];
            #pragma unroll
            for (int fm = 0; fm < 4; fm++) {
                const int m = wm * 64 + fm * 16 + g;
                ah[fm][0] = __float_as_uint(pAh[kk * AST + m]);
                ah[fm][1] = __float_as_uint(pAh[kk * AST + m + 8]);
                ah[fm][2] = __float_as_uint(pAh[(kk + 4) * AST + m]);
                ah[fm][3] = __float_as_uint(pAh[(kk + 4) * AST + m + 8]);
                al[fm][0] = __float_as_uint(pAl[kk * AST + m]);
                al[fm][1] = __float_as_uint(pAl[kk * AST + m + 8]);
                al[fm][2] = __float_as_uint(pAl[(kk + 4) * AST + m]);
                al[fm][3] = __float_as_uint(pAl[(kk + 4) * AST + m + 8]);
            }
            #pragma unroll
            for (int fn = 0; fn < 4; fn++) {
                const int n = wn * 32 + fn * 8 + g;
                bv[fn][0] = __float_as_uint(pV[kk * AST + n]);
                bv[fn][1] = __float_as_uint(pV[(kk + 4) * AST + n]);
            }
            #pragma unroll
            for (int fm = 0; fm < 4; fm++)
                #pragma unroll
                for (int fn = 0; fn < 4; fn++) {
                    mma_tf32(acc[fm][fn], ah[fm], bv[fn]);
                    mma_tf32(acc[fm][fn], al[fm], bv[fn]);
                }
        }
    }

    #pragma unroll
    for (int fm = 0; fm < 4; fm++) {
        #pragma unroll
        for (int half = 0; half < 2; half++) {
            const int j = j0 + wm * 64 + fm * 16 + g + half * 8;
            #pragma unroll
            for (int fn = 0; fn < 4; fn++) {
                const int d = d0 + wn * 32 + fn * 8 + 2 * tig;
                #pragma unroll
                for (int c = 0; c < 2; c++) {
                    const float v = acc[fm][fn][half * 2 + c];
                    const float h = tf32f(v);
                    g_y0h[(size_t)j * DDIM + d + c] = h;
                    g_y0l[(size_t)j * DDIM + d + c] = tf32f(v - h);
                }
            }
        }
    }
}

// =====================================================================
extern "C" void kernel_launch(void* const* d_in, const int* in_sizes, int n_in,
                              void* d_out, int out_size)
{
    const float* x  = (const float*)d_in[0];
    const float* Wq = (const float*)d_in[1];
    const float* Wk = (const float*)d_in[2];
    const float* Wv = (const float*)d_in[3];
    const float* Wo = (const float*)d_in[4];

    float *xh, *xl, *Wqh, *Wql, *Wkh, *Wkl, *Wvr, *Wor, *Qp, *Kp, *Vp, *y0h, *y0l;
    cudaGetSymbolAddress((void**)&xh,  g_xh);
    cudaGetSymbolAddress((void**)&xl,  g_xl);
    cudaGetSymbolAddress((void**)&Wqh, g_Wqh);
    cudaGetSymbolAddress((void**)&Wql, g_Wql);
    cudaGetSymbolAddress((void**)&Wkh, g_Wkh);
    cudaGetSymbolAddress((void**)&Wkl, g_Wkl);
    cudaGetSymbolAddress((void**)&Wvr, g_Wvr);
    cudaGetSymbolAddress((void**)&Wor, g_Wor);
    cudaGetSymbolAddress((void**)&Qp,  g_Q);
    cudaGetSymbolAddress((void**)&Kp,  g_K);
    cudaGetSymbolAddress((void**)&Vp,  g_V);
    cudaGetSymbolAddress((void**)&y0h, g_y0h);
    cudaGetSymbolAddress((void**)&y0l, g_y0l);

    const size_t yel = (size_t)NTOK * DDIM;
    const size_t ael = (size_t)NTOK * NTOK;
    float* d_y;
    float* d_att;
    int write_att;
    if ((size_t)out_size >= yel + ael) {
        d_y = (float*)d_out;
        d_att = (float*)d_out + yel;
        write_att = 1;
    } else if ((size_t)out_size >= ael) {
        d_y = Qp;
        d_att = (float*)d_out;
        write_att = 1;
    } else {
        d_y = (float*)d_out;
        d_att = nullptr;
        write_att = 0;
    }

    // opt-in dynamic smem (idempotent; not a stream op, capture-safe)
    cudaFuncSetAttribute(gemm_pipe<1,1,1>, cudaFuncAttributeMaxDynamicSharedMemorySize, 8 * ETS * 4);
    cudaFuncSetAttribute(gemm_pipe<1,0,1>, cudaFuncAttributeMaxDynamicSharedMemorySize, 6 * ETS * 4);
    cudaFuncSetAttribute(gemm_pipe<1,0,0>, cudaFuncAttributeMaxDynamicSharedMemorySize, 6 * ETS * 4);
    cudaFuncSetAttribute(attv_mma,         cudaFuncAttributeMaxDynamicSharedMemorySize, 6 * ATS * 4);

    const int n1 = NTOK * DDIM;
    const int n2 = DDIM * DDIM;
    split_k<<<n1 / 256, 256>>>(x,  xh,  xl,  n1);
    split_k<<<n2 / 256, 256>>>(Wq, Wqh, Wql, n2);
    split_k<<<n2 / 256, 256>>>(Wk, Wkh, Wkl, n2);
    round_k<<<n2 / 256, 256>>>(Wv, Wvr, n2);
    round_k<<<n2 / 256, 256>>>(Wo, Wor, n2);

    const dim3 gP(DDIM / 128, NTOK / 128);   // (8, 64)

    // Q, K: 3-term (near-fp32), outputs tf32-rounded for the band stage
    gemm_pipe<1,1,1><<<gP, 256, 8 * ETS * 4>>>(xh, xl, Wqh, Wql, Qp, nullptr,
                                               NTOK, DDIM, DDIM, 0.06f);
    gemm_pipe<1,1,1><<<gP, 256, 8 * ETS * 4>>>(xh, xl, Wkh, Wkl, Kp, nullptr,
                                               NTOK, DDIM, DDIM, 1.0f);
    // V: 2-term, output tf32-rounded for attv
    gemm_pipe<1,0,1><<<gP, 256, 6 * ETS * 4>>>(xh, xl, Wvr, nullptr, Vp, nullptr,
                                               NTOK, DDIM, DDIM, 1.0f);

    // banded logits (single tf32 on exact-tf32 operands)
    qk_mma<<<dim3(5, NTOK / 128), 256>>>();

    if (write_att)
        cudaMemsetAsync(d_att, 0, ael * sizeof(float));
    softmax_band_kernel<<<NTOK, 256>>>(d_att, write_att);

    // y0 = att^T @ V  (2-term: att split), output split for Wo stage
    attv_mma<<<dim3(DDIM / 128, NTOK / 128), 256, 6 * ATS * 4>>>();

    // y = y0 @ Wo^T (2-term: y0 split)
    gemm_pipe<1,0,0><<<gP, 256, 6 * ETS * 4>>>(y0h, y0l, Wor, nullptr, d_y, nullptr,
                                               NTOK, DDIM, DDIM, 1.0f);
}